// round 2
// baseline (speedup 1.0000x reference)
#include <cuda_runtime.h>
#include <cstdint>

#define TS 47   // timesteps (T-1)

// ---------------- device scratch (allocation-free) ----------------
__device__ __align__(128) float g_features[8192 * 256];
__device__ __align__(128) float g_featw1 [8192 * 512];
__device__ __align__(128) float g_embtok [6016 * 256];
__device__ __align__(128) float g_embmx  [6016 * 1536];
__device__ __align__(128) float g_mx     [128 * 1536];
__device__ __align__(128) float g_hidw2  [2 * 128 * 512];   // two K-split halves
__device__ __align__(128) float g_context[128 * 256];
__device__ __align__(128) float g_states [6016 * 512];
__device__ __align__(128) float g_fc1out [6016 * 512];

__device__ __forceinline__ float tanh_apx(float x) {
    float y;
    asm("tanh.approx.f32 %0, %1;" : "=f"(y) : "f"(x));
    return y;
}

// ---------------- big GEMM: 128x128 tile, BK=8, 8x8 micro ----------------
// C[M,N] = act(A[M,K] @ B[K,N] + bias). M%128==0, K%8==0. N guarded.
// remap: A-row (t*128+b) stored to C-row (b*47+t)  (fc2 transpose fusion).
__global__ __launch_bounds__(256) void sgemm128(
    const float* __restrict__ A, const float* __restrict__ B,
    const float* __restrict__ bias, float* __restrict__ C,
    int M, int N, int K, int relu, int remap)
{
    __shared__ float As[8][128];
    __shared__ float Bs[8][128];

    int tid = threadIdx.x;
    int bm = blockIdx.y * 128;
    int bn = blockIdx.x * 128;
    int ar = tid >> 1;            // 0..127
    int ac = (tid & 1) * 4;       // 0 or 4
    int br = tid >> 5;            // 0..7
    int bc = (tid & 31) * 4;      // 0..124
    int tx = tid & 15, ty = tid >> 4;

    float acc[8][8] = {};
    const float* Ap = A + (size_t)(bm + ar) * K + ac;

    for (int k0 = 0; k0 < K; k0 += 8) {
        float4 av = *(const float4*)(Ap + k0);
        As[ac + 0][ar] = av.x;
        As[ac + 1][ar] = av.y;
        As[ac + 2][ar] = av.z;
        As[ac + 3][ar] = av.w;

        int gc = bn + bc;
        const float* Bp = B + (size_t)(k0 + br) * N + gc;
        float4 bv;
        if (gc + 3 < N) {
            bv = *(const float4*)Bp;
        } else {
            bv.x = (gc + 0 < N) ? Bp[0] : 0.f;
            bv.y = (gc + 1 < N) ? Bp[1] : 0.f;
            bv.z = (gc + 2 < N) ? Bp[2] : 0.f;
            bv.w = (gc + 3 < N) ? Bp[3] : 0.f;
        }
        *(float4*)&Bs[br][bc] = bv;
        __syncthreads();

        #pragma unroll
        for (int k = 0; k < 8; k++) {
            float a[8], b[8];
            float4 a0 = *(const float4*)&As[k][ty * 4];
            float4 a1 = *(const float4*)&As[k][64 + ty * 4];
            float4 b0 = *(const float4*)&Bs[k][tx * 4];
            float4 b1 = *(const float4*)&Bs[k][64 + tx * 4];
            a[0]=a0.x; a[1]=a0.y; a[2]=a0.z; a[3]=a0.w;
            a[4]=a1.x; a[5]=a1.y; a[6]=a1.z; a[7]=a1.w;
            b[0]=b0.x; b[1]=b0.y; b[2]=b0.z; b[3]=b0.w;
            b[4]=b1.x; b[5]=b1.y; b[6]=b1.z; b[7]=b1.w;
            #pragma unroll
            for (int i = 0; i < 8; i++)
                #pragma unroll
                for (int j = 0; j < 8; j++)
                    acc[i][j] = fmaf(a[i], b[j], acc[i][j]);
        }
        __syncthreads();
    }

    #pragma unroll
    for (int i = 0; i < 8; i++) {
        int grow = bm + ((i < 4) ? (ty * 4 + i) : (64 + ty * 4 + i - 4));
        size_t ro;
        if (remap) {
            int t = grow >> 7, b = grow & 127;
            ro = ((size_t)b * TS + t) * (size_t)N;
        } else {
            ro = (size_t)grow * (size_t)N;
        }
        #pragma unroll
        for (int j = 0; j < 8; j++) {
            int gc = bn + ((j < 4) ? (tx * 4 + j) : (64 + tx * 4 + j - 4));
            if (gc < N) {
                float v = acc[i][j] + (bias ? bias[gc] : 0.f);
                if (relu) v = fmaxf(v, 0.f);
                C[ro + gc] = v;
            }
        }
    }
}

// ---------------- per-step small GEMM: 32x32 tile, BK=16, 2x2 micro ----------------
// M fixed 128 (grid.y=4). Optional K-split via grid.z: block z handles
// k in [z*KC, (z+1)*KC), writes to C + z*zstride. lda = full K of A.
__global__ __launch_bounds__(256) void sgemm_step(
    const float* __restrict__ A, const float* __restrict__ B,
    float* __restrict__ C, int N, int lda, int KC, size_t zstride)
{
    __shared__ float As[16][32];
    __shared__ float Bs[16][32];

    int tid = threadIdx.x;
    int bm = blockIdx.y * 32;
    int bn = blockIdx.x * 32;
    int kbeg = blockIdx.z * KC;
    C += (size_t)blockIdx.z * zstride;

    int arow = tid >> 3;           // 0..31
    int akc  = (tid & 7) * 2;      // 0..14
    int bkr  = tid >> 4;           // 0..15
    int bnc  = (tid & 15) * 2;     // 0..30
    int tx = tid & 15, ty = tid >> 4;

    float acc00 = 0.f, acc01 = 0.f, acc10 = 0.f, acc11 = 0.f;

    for (int k0 = kbeg; k0 < kbeg + KC; k0 += 16) {
        float2 av = *(const float2*)(A + (size_t)(bm + arow) * lda + k0 + akc);
        As[akc + 0][arow] = av.x;
        As[akc + 1][arow] = av.y;
        float2 bv = *(const float2*)(B + (size_t)(k0 + bkr) * N + bn + bnc);
        Bs[bkr][bnc + 0] = bv.x;
        Bs[bkr][bnc + 1] = bv.y;
        __syncthreads();

        #pragma unroll
        for (int k = 0; k < 16; k++) {
            float2 a = *(const float2*)&As[k][ty * 2];
            float2 b = *(const float2*)&Bs[k][tx * 2];
            acc00 = fmaf(a.x, b.x, acc00);
            acc01 = fmaf(a.x, b.y, acc01);
            acc10 = fmaf(a.y, b.x, acc10);
            acc11 = fmaf(a.y, b.y, acc11);
        }
        __syncthreads();
    }

    int r0 = bm + ty * 2, c0 = bn + tx * 2;
    C[(size_t)(r0 + 0) * N + c0 + 0] = acc00;
    C[(size_t)(r0 + 0) * N + c0 + 1] = acc01;
    C[(size_t)(r0 + 1) * N + c0 + 0] = acc10;
    C[(size_t)(r0 + 1) * N + c0 + 1] = acc11;
}

// ---------------- token embedding gather ----------------
__global__ void gather_kernel(const int* __restrict__ target,
                              const float* __restrict__ emb)
{
    int row = blockIdx.x;          // t*128 + b, 6016 rows
    int e = threadIdx.x;           // 256
    int t = row >> 7, b = row & 127;
    int tok = (t == 0) ? 1 : target[b * 48 + t];
    g_embtok[(size_t)row * 256 + e] = emb[(size_t)tok * 256 + e];
}

// ---------------- fused Bahdanau attention (one block per batch element) ----------------
__global__ __launch_bounds__(256) void attention_kernel(
    const float* __restrict__ V, const float* __restrict__ bV,
    const float* __restrict__ b2)
{
    int b = blockIdx.x, tid = threadIdx.x;
    __shared__ float sh_hw2[512];
    __shared__ float sh_V[512];
    __shared__ float sh_l[64];

    sh_hw2[tid]       = g_hidw2[b * 512 + tid]       + g_hidw2[65536 + b * 512 + tid]       + b2[tid];
    sh_hw2[tid + 256] = g_hidw2[b * 512 + tid + 256] + g_hidw2[65536 + b * 512 + tid + 256] + b2[tid + 256];
    sh_V[tid] = V[tid];
    sh_V[tid + 256] = V[tid + 256];
    __syncthreads();

    int w = tid >> 5, lane = tid & 31;
    #pragma unroll
    for (int p = 0; p < 8; p++) {
        int l = w * 8 + p;
        const float* row = g_featw1 + ((size_t)b * 64 + l) * 512;
        float a = 0.f;
        #pragma unroll
        for (int j = 0; j < 16; j++) {
            int u = lane + j * 32;
            float s = tanh_apx(row[u] + sh_hw2[u]);
            a = fmaf(s, sh_V[u], a);
        }
        #pragma unroll
        for (int o = 16; o; o >>= 1) a += __shfl_xor_sync(0xffffffffu, a, o);
        if (lane == 0) sh_l[l] = a + bV[0];
    }
    __syncthreads();

    if (tid < 32) {
        float v0 = sh_l[tid], v1 = sh_l[tid + 32];
        float m = fmaxf(v0, v1);
        #pragma unroll
        for (int o = 16; o; o >>= 1) m = fmaxf(m, __shfl_xor_sync(0xffffffffu, m, o));
        float e0 = __expf(v0 - m), e1 = __expf(v1 - m);
        float s = e0 + e1;
        #pragma unroll
        for (int o = 16; o; o >>= 1) s += __shfl_xor_sync(0xffffffffu, s, o);
        float inv = 1.0f / s;
        sh_l[tid] = e0 * inv;
        sh_l[tid + 32] = e1 * inv;
    }
    __syncthreads();

    float c = 0.f;
    #pragma unroll 8
    for (int l = 0; l < 64; l++)
        c = fmaf(sh_l[l], g_features[((size_t)b * 64 + l) * 256 + tid], c);
    g_context[b * 256 + tid] = c;
}

// ---------------- GRU pointwise (zero initial state => gru_rk dead) ----------------
__global__ void gru_kernel(const float* __restrict__ gb, int t)
{
    int b = blockIdx.x, u = threadIdx.x;   // 128 blocks x 512 threads
    size_t r = (size_t)t * 128 + b;
    float xz = g_mx[b * 1536 + u]        + g_embmx[r * 1536 + u];
    float xr = g_mx[b * 1536 + 512 + u]  + g_embmx[r * 1536 + 512 + u];
    float xh = g_mx[b * 1536 + 1024 + u] + g_embmx[r * 1536 + 1024 + u];
    float rz = gb[1536 + u];
    float rr = gb[1536 + 512 + u];
    float rh = gb[1536 + 1024 + u];
    float z  = 1.f / (1.f + __expf(-(xz + rz)));
    float rg = 1.f / (1.f + __expf(-(xr + rr)));
    float hh = tanhf(xh + rg * rh);
    g_states[r * 512 + u] = (1.f - z) * hh;
}

// ---------------- launch ----------------
extern "C" void kernel_launch(void* const* d_in, const int* in_sizes, int n_in,
                              void* d_out, int out_size)
{
    const float* img    = (const float*)d_in[0];
    const int*   target = (const int*)  d_in[1];
    const float* W_fc   = (const float*)d_in[2];
    const float* b_fc   = (const float*)d_in[3];
    const float* W1     = (const float*)d_in[4];
    const float* b1     = (const float*)d_in[5];
    const float* W2     = (const float*)d_in[6];
    const float* b2     = (const float*)d_in[7];
    const float* V      = (const float*)d_in[8];
    const float* bV     = (const float*)d_in[9];
    const float* emb    = (const float*)d_in[10];
    const float* gru_k  = (const float*)d_in[11];
    /* d_in[12] = gru_rk : dead (zero GRU state) */
    const float* gru_b  = (const float*)d_in[13];
    const float* fc1_w  = (const float*)d_in[14];
    const float* fc1_b  = (const float*)d_in[15];
    const float* fc2_w  = (const float*)d_in[16];
    const float* fc2_b  = (const float*)d_in[17];
    float* out = (float*)d_out;

    float *features, *featw1, *embtok, *embmx, *mx, *hidw2, *context, *states, *fc1out;
    cudaGetSymbolAddress((void**)&features, g_features);
    cudaGetSymbolAddress((void**)&featw1,  g_featw1);
    cudaGetSymbolAddress((void**)&embtok,  g_embtok);
    cudaGetSymbolAddress((void**)&embmx,   g_embmx);
    cudaGetSymbolAddress((void**)&mx,      g_mx);
    cudaGetSymbolAddress((void**)&hidw2,   g_hidw2);
    cudaGetSymbolAddress((void**)&context, g_context);
    cudaGetSymbolAddress((void**)&states,  g_states);
    cudaGetSymbolAddress((void**)&fc1out,  g_fc1out);

    // encoder: features = relu(img @ W_fc + b_fc)   (8192x2048)@(2048x256)
    sgemm128<<<dim3(2, 64), 256>>>(img, W_fc, b_fc, features, 8192, 256, 2048, 1, 0);
    // featw1 = features @ W1 + b1                  (8192x256)@(256x512)
    sgemm128<<<dim3(4, 64), 256>>>(features, W1, b1, featw1, 8192, 512, 256, 0, 0);
    // token embeddings for all 47 steps
    gather_kernel<<<6016, 256>>>(target, emb);
    // embmx = embtok @ gru_k[256:,:] + gru_b[0]    (6016x256)@(256x1536)
    sgemm128<<<dim3(12, 47), 256>>>(embtok, gru_k + 256 * 1536, gru_b, embmx, 6016, 1536, 256, 0, 0);
    // zero hidden@W2 halves for step 0 (hidden0 = 0)
    cudaMemsetAsync(hidw2, 0, 2 * 128 * 512 * sizeof(float));

    for (int t = 0; t < TS; t++) {
        if (t > 0) {
            // hidw2 halves = states[t-1] @ W2 (K split 256+256)
            sgemm_step<<<dim3(16, 4, 2), 256>>>(
                states + (size_t)(t - 1) * 128 * 512, W2, hidw2,
                512, 512, 256, (size_t)128 * 512);
        }
        attention_kernel<<<128, 256>>>(V, bV, b2);
        // mx = context @ gru_k[:256,:]             (128x256)@(256x1536)
        sgemm_step<<<dim3(48, 4, 1), 256>>>(context, gru_k, mx, 1536, 256, 256, 0);
        gru_kernel<<<128, 512>>>(gru_b, t);
    }

    // fc1out = states @ fc1_w + fc1_b              (6016x512)@(512x512)
    sgemm128<<<dim3(4, 47), 256>>>(states, fc1_w, fc1_b, fc1out, 6016, 512, 512, 0, 0);
    // out = fc1out @ fc2_w + fc2_b, remapped to (B, 47, VOCAB)
    sgemm128<<<dim3(40, 47), 256>>>(fc1out, fc2_w, fc2_b, out, 6016, 5000, 512, 0, 1);
}